// round 1
// baseline (speedup 1.0000x reference)
#include <cuda_runtime.h>

// out[n][c] = in[n][c] + glob[batch[n]][c]
// N = 1,000,000 points, C = 128 channels, B = 8 batches, all fp32.
// Memory-bound streaming kernel: ~1.03 GB moved -> ~130 us floor @ 8 TB/s.

static constexpr int C_VEC = 128 / 4;  // 32 float4 per row

__global__ __launch_bounds__(256)
void sparse_global_broadcast_kernel(const float4* __restrict__ in,
                                    const float4* __restrict__ glob,
                                    const int*    __restrict__ bidx,
                                    float4*       __restrict__ out,
                                    long long n_vec) {
    long long i = (long long)blockIdx.x * blockDim.x + threadIdx.x;
    if (i >= n_vec) return;

    int row  = (int)(i >> 5);          // i / 32  (C/4 = 32)
    int lane = (int)(i & 31);          // channel-vec within row

    int b = __ldg(&bidx[row]);         // broadcast across the 32 lanes of a row
    float4 a = __ldg(&in[i]);
    float4 g = __ldg(&glob[(long long)b * C_VEC + lane]);  // 4 KB table, L1-resident

    float4 r;
    r.x = a.x + g.x;
    r.y = a.y + g.y;
    r.z = a.z + g.z;
    r.w = a.w + g.w;
    out[i] = r;
}

extern "C" void kernel_launch(void* const* d_in, const int* in_sizes, int n_in,
                              void* d_out, int out_size) {
    const float4* in   = (const float4*)d_in[0];   // input_features   [N, C]
    const float4* glob = (const float4*)d_in[1];   // input_features_global [B, C]
    const int*    bidx = (const int*)d_in[2];      // batch_indices    [N]

    float4* out = (float4*)d_out;

    long long n_elems = (long long)in_sizes[0];    // N * C
    long long n_vec   = n_elems / 4;               // float4 count

    int threads = 256;
    long long blocks = (n_vec + threads - 1) / threads;

    sparse_global_broadcast_kernel<<<(unsigned)blocks, threads>>>(in, glob, bidx, out, n_vec);
}

// round 2
// speedup vs baseline: 1.2144x; 1.2144x over previous
#include <cuda_runtime.h>

// out[n][c] = in[n][c] + glob[batch[n]][c]
// N = 1,000,000 points, C = 128 channels, B = 8 batches, all fp32.
// ~1.03 GB streamed -> ~130 us floor @ 8 TB/s HBM3e.
//
// R2: ILP=4 per thread (4 independent LDG.128 front-batched) to raise MLP,
//     streaming cache hints on the big tensors, glob kept L1-cached.

static constexpr int C_VEC  = 128 / 4;  // 32 float4 per row
static constexpr int UNROLL = 4;

__global__ __launch_bounds__(256)
void sparse_global_broadcast_kernel(const float4* __restrict__ in,
                                    const float4* __restrict__ glob,
                                    const int*    __restrict__ bidx,
                                    float4*       __restrict__ out,
                                    long long n_vec) {
    long long base = (long long)blockIdx.x * (blockDim.x * UNROLL) + threadIdx.x;

    long long idx[UNROLL];
    float4 a[UNROLL];
    int    b[UNROLL];
    bool   ok[UNROLL];

    // Front-batch all independent loads: 4x LDG.128 (streaming) + 4x LDG.32 (bidx).
    #pragma unroll
    for (int u = 0; u < UNROLL; u++) {
        idx[u] = base + (long long)u * blockDim.x;
        ok[u]  = idx[u] < n_vec;
        if (ok[u]) {
            a[u] = __ldcs(&in[idx[u]]);                 // evict-first: pure stream
            b[u] = __ldg(&bidx[(int)(idx[u] >> 5)]);    // warp-broadcast, cache
        }
    }

    #pragma unroll
    for (int u = 0; u < UNROLL; u++) {
        if (ok[u]) {
            int lane = (int)(idx[u] & 31);
            float4 g = __ldg(&glob[b[u] * C_VEC + lane]);  // 4 KB table, L1-resident
            float4 r;
            r.x = a[u].x + g.x;
            r.y = a[u].y + g.y;
            r.z = a[u].z + g.z;
            r.w = a[u].w + g.w;
            __stcs(&out[idx[u]], r);                    // streaming store
        }
    }
}

extern "C" void kernel_launch(void* const* d_in, const int* in_sizes, int n_in,
                              void* d_out, int out_size) {
    const float4* in   = (const float4*)d_in[0];   // input_features        [N, C]
    const float4* glob = (const float4*)d_in[1];   // input_features_global [B, C]
    const int*    bidx = (const int*)d_in[2];      // batch_indices         [N]

    float4* out = (float4*)d_out;

    long long n_elems = (long long)in_sizes[0];    // N * C
    long long n_vec   = n_elems / 4;               // float4 count

    int threads = 256;
    long long per_block = (long long)threads * UNROLL;
    long long blocks = (n_vec + per_block - 1) / per_block;

    sparse_global_broadcast_kernel<<<(unsigned)blocks, threads>>>(in, glob, bidx, out, n_vec);
}